// round 13
// baseline (speedup 1.0000x reference)
#include <cuda_runtime.h>
#include <cuda_bf16.h>
#include <cstdint>

// ---------------------------------------------------------------------------
#define M_Q   2048
#define N_V   131072
#define DIM   256
#define BM    128
#define BN    128
#define BK    32
#define NBLK  (N_V / BN)          // 1024 (partials stay in 128-col blocks)
#define QBLK  (M_Q / BM)          // 16
#define NTILE2 256                // tcgen05 tile N
#define NBLK2  (N_V / NTILE2)     // 512
#define MARGIN 3.0f

// tcgen05 legal only in arch/family-specific passes
#if defined(__CUDA_ARCH__) && ( \
      (defined(__CUDA_ARCH_SPECIFIC__)        && (__CUDA_ARCH_SPECIFIC__        >= 1000)) || \
      (defined(__CUDA_ARCH_FAMILY_SPECIFIC__) && (__CUDA_ARCH_FAMILY_SPECIFIC__ >= 1000)) || \
      defined(__CUDA_ARCH_FEAT_SM100_ALL) || defined(__CUDA_ARCH_FEAT_SM103_ALL))
#define TCG_PATH 1
#else
#define TCG_PATH 0
#endif

// ---------------------------------------------------------------------------
// Device-global scratch
// ---------------------------------------------------------------------------
__device__ __nv_bfloat16 g_Vb[(size_t)N_V * DIM];
__device__ __nv_bfloat16 g_Qb[(size_t)M_Q * DIM];
__device__ float g_vsq[N_V];
__device__ float g_pv1[M_Q * NBLK];
__device__ float g_pv2[M_Q * NBLK];
__device__ int   g_pi1[M_Q * NBLK];
__device__ int   g_pi2[M_Q * NBLK];
__device__ int   g_tc_bad;

// ---------------------------------------------------------------------------
__device__ __forceinline__ uint32_t smem_u32(const void* p) {
    uint32_t a;
    asm("{ .reg .u64 t; cvta.to.shared.u64 t, %1; cvt.u32.u64 %0, t; }" : "=r"(a) : "l"(p));
    return a;
}

__global__ void zero_flag_kernel() { g_tc_bad = 0; }

// ---------------------------------------------------------------------------
// Convert kernels: fp32 -> bf16 (+ ||v||^2)
// ---------------------------------------------------------------------------
__global__ void convert_vec_kernel(const float* __restrict__ src) {
    int warp = (blockIdx.x * blockDim.x + threadIdx.x) >> 5;
    int lane = threadIdx.x & 31;
    if (warp >= N_V) return;
    const float4* s = reinterpret_cast<const float4*>(src + (size_t)warp * DIM);
    uint2* d = reinterpret_cast<uint2*>(g_Vb + (size_t)warp * DIM);
    float acc = 0.f;
#pragma unroll
    for (int i = 0; i < 2; i++) {
        float4 f = s[lane + 32 * i];
        acc += f.x * f.x + f.y * f.y + f.z * f.z + f.w * f.w;
        __nv_bfloat162 lo = __floats2bfloat162_rn(f.x, f.y);
        __nv_bfloat162 hi = __floats2bfloat162_rn(f.z, f.w);
        uint2 u;
        u.x = *reinterpret_cast<uint32_t*>(&lo);
        u.y = *reinterpret_cast<uint32_t*>(&hi);
        d[lane + 32 * i] = u;
    }
#pragma unroll
    for (int o = 16; o; o >>= 1) acc += __shfl_xor_sync(0xFFFFFFFFu, acc, o);
    if (lane == 0) g_vsq[warp] = acc;
}

__global__ void convert_q_kernel(const float* __restrict__ src) {
    int warp = (blockIdx.x * blockDim.x + threadIdx.x) >> 5;
    int lane = threadIdx.x & 31;
    if (warp >= M_Q) return;
    const float4* s = reinterpret_cast<const float4*>(src + (size_t)warp * DIM);
    uint2* d = reinterpret_cast<uint2*>(g_Qb + (size_t)warp * DIM);
#pragma unroll
    for (int i = 0; i < 2; i++) {
        float4 f = s[lane + 32 * i];
        __nv_bfloat162 lo = __floats2bfloat162_rn(f.x, f.y);
        __nv_bfloat162 hi = __floats2bfloat162_rn(f.z, f.w);
        uint2 u;
        u.x = *reinterpret_cast<uint32_t*>(&lo);
        u.y = *reinterpret_cast<uint32_t*>(&hi);
        d[lane + 32 * i] = u;
    }
}

// ---------------------------------------------------------------------------
__device__ __forceinline__ void top2_upd(float v, int idx, float& v1, int& i1,
                                         float& v2, int& i2) {
    if (v < v1) { v2 = v1; i2 = i1; v1 = v; i1 = idx; }
    else if (v < v2) { v2 = v; i2 = idx; }
}

__device__ __forceinline__ void top2_shfl_merge(float& v1, int& i1, float& v2,
                                                int& i2, int m) {
    float ov1 = __shfl_xor_sync(0xFFFFFFFFu, v1, m);
    float ov2 = __shfl_xor_sync(0xFFFFFFFFu, v2, m);
    int   oi1 = __shfl_xor_sync(0xFFFFFFFFu, i1, m);
    int   oi2 = __shfl_xor_sync(0xFFFFFFFFu, i2, m);
    if (ov1 < v1) {
        if (v1 < ov2) { v2 = v1; i2 = i1; } else { v2 = ov2; i2 = oi2; }
        v1 = ov1; i1 = oi1;
    } else {
        if (ov1 < v2) { v2 = ov1; i2 = oi1; }
    }
}

// ---------------------------------------------------------------------------
// tcgen05 helpers (arch-specific pass only)
// ---------------------------------------------------------------------------
#if TCG_PATH
__device__ __forceinline__ uint32_t elect_one_pred() {
    uint32_t pred;
    asm volatile("{\n\t.reg .pred p;\n\telect.sync _|p, 0xFFFFFFFF;\n\tselp.b32 %0, 1, 0, p;\n\t}" : "=r"(pred));
    return pred;
}
#define TCGEN05_ALLOC(sm, n) \
    asm volatile("tcgen05.alloc.cta_group::1.sync.aligned.shared::cta.b32 [%0], %1;" :: "r"((uint32_t)(sm)), "r"((uint32_t)(n)) : "memory")
#define TCGEN05_DEALLOC(t, n) \
    asm volatile("tcgen05.dealloc.cta_group::1.sync.aligned.b32 %0, %1;" :: "r"(t), "r"((uint32_t)(n)))
#define TCGEN05_RELINQUISH() \
    asm volatile("tcgen05.relinquish_alloc_permit.cta_group::1.sync.aligned;")
#define TCGEN05_COMMIT(mb) \
    asm volatile("tcgen05.commit.cta_group::1.mbarrier::arrive::one.shared::cluster.b64 [%0];" :: "r"((uint32_t)(mb)) : "memory")
#define TCGEN05_FENCE_AFTER() \
    asm volatile("tcgen05.fence::after_thread_sync;" ::: "memory")
#define TCGEN05_WAIT_LD() \
    asm volatile("tcgen05.wait::ld.sync.aligned;" ::: "memory")
#define MBARRIER_INIT(mb, cnt) \
    asm volatile("mbarrier.init.shared.b64 [%0], %1;" :: "r"((uint32_t)(mb)), "r"((uint32_t)(cnt)) : "memory")
#define FENCE_PROXY_ASYNC() \
    asm volatile("fence.proxy.async.shared::cta;" ::: "memory")

#define MBARRIER_WAIT_PARITY(mb, par) do {                                          \
    uint32_t _mb = (uint32_t)(mb); uint32_t _p = (uint32_t)(par); uint32_t _done;   \
    asm volatile("{\n\t.reg .pred p;\n\t"                                           \
        "mbarrier.try_wait.parity.acquire.cta.shared::cta.b64 p, [%1], %2;\n\t"     \
        "selp.b32 %0, 1, 0, p;\n\t}" : "=r"(_done) : "r"(_mb), "r"(_p) : "memory"); \
    if (!_done) {                                                                   \
        asm volatile("{\n\t.reg .pred P1;\n\t"                                      \
            "WL_%=:\n\t"                                                            \
            "mbarrier.try_wait.parity.acquire.cta.shared::cta.b64 P1, [%0], %1, 0x989680;\n\t" \
            "@P1 bra.uni WD_%=;\n\t"                                                \
            "bra.uni WL_%=;\n\t"                                                    \
            "WD_%=:\n\t}" :: "r"(_mb), "r"(_p) : "memory");                         \
    }                                                                               \
} while (0)

#define TCGEN05_LD_32X32B_X32(r, ta) \
    asm volatile( \
        "tcgen05.ld.sync.aligned.32x32b.x32.b32 " \
        "{%0, %1, %2, %3, %4, %5, %6, %7, " \
        " %8, %9, %10, %11, %12, %13, %14, %15, " \
        " %16, %17, %18, %19, %20, %21, %22, %23, " \
        " %24, %25, %26, %27, %28, %29, %30, %31}, [%32];" \
        : "=r"((r)[0]),  "=r"((r)[1]),  "=r"((r)[2]),  "=r"((r)[3]), \
          "=r"((r)[4]),  "=r"((r)[5]),  "=r"((r)[6]),  "=r"((r)[7]), \
          "=r"((r)[8]),  "=r"((r)[9]),  "=r"((r)[10]), "=r"((r)[11]), \
          "=r"((r)[12]), "=r"((r)[13]), "=r"((r)[14]), "=r"((r)[15]), \
          "=r"((r)[16]), "=r"((r)[17]), "=r"((r)[18]), "=r"((r)[19]), \
          "=r"((r)[20]), "=r"((r)[21]), "=r"((r)[22]), "=r"((r)[23]), \
          "=r"((r)[24]), "=r"((r)[25]), "=r"((r)[26]), "=r"((r)[27]), \
          "=r"((r)[28]), "=r"((r)[29]), "=r"((r)[30]), "=r"((r)[31]) \
        : "r"(ta))

static constexpr uint64_t SMEM_DESC_BASE_SW128 =
    (uint64_t(2) << 61) | (uint64_t(1) << 46) | (uint64_t(64) << 32) | (uint64_t(1) << 16);
#define MAKE_SMEM_DESC(a) (SMEM_DESC_BASE_SW128 | ((uint64_t)((a) >> 4) & 0x3FFF))
#define SW128(b) ((b) ^ (((b) >> 3) & 0x70))

__device__ __forceinline__ void mma_bf16_ss(uint32_t d_tmem, uint64_t a_desc,
                                            uint64_t b_desc, uint32_t idesc,
                                            uint32_t enable) {
    asm volatile(
        "{\n\t.reg .pred p;\n\t"
        "setp.ne.u32 p, %4, 0;\n\t"
        "tcgen05.mma.cta_group::1.kind::f16 [%0], %1, %2, %3, {%5, %5, %5, %5}, p;\n\t"
        "}"
        :: "r"(d_tmem), "l"(a_desc), "l"(b_desc), "r"(idesc), "r"(enable), "r"(0u)
        : "memory");
}

// idesc: dtype=F32(bit4), atype=BF16(bit7), btype=BF16(bit10), N=256, M=128
// (cross-checked vs test_mma.cu literal 0x8080490 for M=128,N=32)
static constexpr uint32_t MMA_IDESC =
    (1u << 4) | (1u << 7) | (1u << 10) | ((NTILE2 / 8) << 17) | ((BM / 16) << 24);
#endif  // TCG_PATH

// ---------------------------------------------------------------------------
// HMMA + cp.async helpers
// ---------------------------------------------------------------------------
__device__ __forceinline__ void mma16816(float* c, const uint32_t* a, const uint32_t* b) {
    asm volatile(
        "mma.sync.aligned.m16n8k16.row.col.f32.bf16.bf16.f32 "
        "{%0,%1,%2,%3}, {%4,%5,%6,%7}, {%8,%9}, {%0,%1,%2,%3};"
        : "+f"(c[0]), "+f"(c[1]), "+f"(c[2]), "+f"(c[3])
        : "r"(a[0]), "r"(a[1]), "r"(a[2]), "r"(a[3]), "r"(b[0]), "r"(b[1]));
}

__device__ __forceinline__ void ldsm_x4(uint32_t& r0, uint32_t& r1, uint32_t& r2,
                                        uint32_t& r3, uint32_t addr) {
    asm volatile("ldmatrix.sync.aligned.m8n8.x4.shared.b16 {%0,%1,%2,%3}, [%4];"
                 : "=r"(r0), "=r"(r1), "=r"(r2), "=r"(r3) : "r"(addr));
}

#define CP_ASYNC16(dst, src) \
    asm volatile("cp.async.cg.shared.global [%0], [%1], 16;" :: "r"(dst), "l"(src))
#define CP_COMMIT() asm volatile("cp.async.commit_group;" ::: "memory")
#define CP_WAIT(n)  asm volatile("cp.async.wait_group %0;" :: "n"(n) : "memory")

// ---------------------------------------------------------------------------
// dist_tc: tcgen05 128x256 tile, K=256 resident, self-validating.
// SMEM: [0]tmem ptr [8]mbar [16]d00, A@1024 (64KB SW128 atoms), B@66560
// (128KB), vsq@197632 (1KB). grid (16, 512), 256 thr.
// ---------------------------------------------------------------------------
#define TG_A_OFF    1024
#define TG_B_OFF    (1024 + 128 * 512)            // 66560
#define TG_VSQ_OFF  (TG_B_OFF + 256 * 512)        // 197632
#define TG_SMEM     (TG_VSQ_OFF + 1024)           // 198656

__global__ void __launch_bounds__(256, 1) dist_tc_kernel() {
#if TCG_PATH
    extern __shared__ char smem[];
    uint32_t sb = smem_u32(smem);
    const int tid = threadIdx.x;
    const int wid = tid >> 5;
    const int lane = tid & 31;
    const int qb = blockIdx.x;
    const int nb = blockIdx.y;

    if (wid == 0) {
        TCGEN05_ALLOC(sb + 0, 256);
        TCGEN05_RELINQUISH();
    }
    if (tid == 0) MBARRIER_INIT(sb + 8, 1);
    __syncthreads();
    uint32_t tmem;
    asm volatile("ld.shared.b32 %0, [%1];" : "=r"(tmem) : "r"(sb + 0));

    // A (128x256 bf16): SW128 atoms (8r x 64c), atom_offset = ar + ac*16
    {
        const uint4* src = reinterpret_cast<const uint4*>(g_Qb + (size_t)qb * BM * DIM);
#pragma unroll 4
        for (int c = tid; c < 4096; c += 256) {
            int row = c >> 5, u = c & 31;
            int ac = u >> 3, iu = u & 7;
            int ar = row >> 3, ir = row & 7;
            uint32_t byt = ((uint32_t)(ac * 16 + ar) << 10) + (ir << 7) + (iu << 4);
            *reinterpret_cast<uint4*>(smem + TG_A_OFF + SW128(byt)) = src[c];
        }
    }
    // B (256x256 bf16): atom_offset = ar + ac*32
    {
        const uint4* src = reinterpret_cast<const uint4*>(g_Vb + (size_t)nb * NTILE2 * DIM);
#pragma unroll 4
        for (int c = tid; c < 8192; c += 256) {
            int row = c >> 5, u = c & 31;
            int ac = u >> 3, iu = u & 7;
            int ar = row >> 3, ir = row & 7;
            uint32_t byt = ((uint32_t)(ac * 32 + ar) << 10) + (ir << 7) + (iu << 4);
            *reinterpret_cast<uint4*>(smem + TG_B_OFF + SW128(byt)) = src[c];
        }
    }
    float* vs = reinterpret_cast<float*>(smem + TG_VSQ_OFF);
    for (int i = tid; i < NTILE2; i += 256) vs[i] = g_vsq[nb * NTILE2 + i];

    FENCE_PROXY_ASYNC();
    __syncthreads();

    if (wid == 0) {
        uint64_t ad = MAKE_SMEM_DESC(sb + TG_A_OFF);
        uint64_t bd = MAKE_SMEM_DESC(sb + TG_B_OFF);
        if (elect_one_pred()) {
#pragma unroll
            for (int k = 0; k < 16; k++) {
                uint64_t ao = ad + (uint64_t)((k >> 2) * 1024 + (k & 3) * 2);
                uint64_t bo = bd + (uint64_t)((k >> 2) * 2048 + (k & 3) * 2);
                mma_bf16_ss(tmem, ao, bo, MMA_IDESC, (uint32_t)(k > 0));
            }
            TCGEN05_COMMIT(sb + 8);
        }
    }
    __syncthreads();
    MBARRIER_WAIT_PARITY(sb + 8, 0);
    TCGEN05_FENCE_AFTER();

    // Epilogue: row = (wid&3)*32+lane; warps 0-3 cols 0..127 (half 0),
    // warps 4-7 cols 128..255 (half 1). Each half = one 128-block partial.
    {
        const int half = wid >> 2;
        const int colbase = half * 128;
        float v1 = 3.4e38f, v2 = 3.4e38f;
        int i1 = 0, i2 = 0;
        uint32_t r[32];
#pragma unroll 1
        for (int b = 0; b < 4; b++) {
            TCGEN05_LD_32X32B_X32(r, tmem + colbase + b * 32);
            TCGEN05_WAIT_LD();
            if (b == 0 && wid == 0 && lane == 0)
                *reinterpret_cast<float*>(smem + 16) = __uint_as_float(r[0]);  // D[0][0]
#pragma unroll
            for (int j = 0; j < 32; j++) {
                int col = colbase + b * 32 + j;
                float val = vs[col] - 2.0f * __uint_as_float(r[j]);
                top2_upd(val, nb * NTILE2 + col, v1, i1, v2, i2);
            }
        }
        int q = qb * BM + (wid & 3) * 32 + lane;
        int pb = nb * 2 + half;
        g_pv1[q * NBLK + pb] = v1;  g_pi1[q * NBLK + pb] = i1;
        g_pv2[q * NBLK + pb] = v2;  g_pi2[q * NBLK + pb] = i2;
    }
    __syncthreads();

    // Self-validation: exact bf16 dot q0.v0 from smem vs TMEM D[0][0]
    if (wid == 0) {
        float ref = 0.f;
#pragma unroll
        for (int t8 = 0; t8 < 8; t8++) {
            int k = lane * 8 + t8;
            uint32_t aoff = ((uint32_t)(k >> 6) << 14) + (uint32_t)(k & 63) * 2;
            uint32_t boff = ((uint32_t)(k >> 6) << 15) + (uint32_t)(k & 63) * 2;
            float a = __bfloat162float(*reinterpret_cast<const __nv_bfloat16*>(smem + TG_A_OFF + aoff));
            float b = __bfloat162float(*reinterpret_cast<const __nv_bfloat16*>(smem + TG_B_OFF + boff));
            ref += a * b;
        }
#pragma unroll
        for (int o = 16; o; o >>= 1) ref += __shfl_xor_sync(0xFFFFFFFFu, ref, o);
        if (lane == 0) {
            float d00 = *reinterpret_cast<float*>(smem + 16);
            if (!(fabsf(d00 - ref) <= 0.5f)) atomicOr(&g_tc_bad, 1);
        }
        TCGEN05_DEALLOC(tmem, 256);
    }
#else
    if (threadIdx.x == 0 && blockIdx.x == 0 && blockIdx.y == 0) g_tc_bad = 1;
#endif
}

// ---------------------------------------------------------------------------
// dist_fb: proven HMMA kernel (round 12); runs only if tcgen05 invalid.
// ---------------------------------------------------------------------------
__global__ void __launch_bounds__(256, 2) dist_fb_kernel() {
    if (*(volatile int*)&g_tc_bad == 0) return;

    __shared__ __nv_bfloat16 As[2][BM][40];
    __shared__ __nv_bfloat16 Bs[2][BN][40];
    __shared__ float vs[BN];
    __shared__ float4 red[BM][2];

    const int tid = threadIdx.x;
    const int wid = tid >> 5;
    const int lane = tid & 31;
    const int g = lane >> 2, tg = lane & 3;
    const int wm = wid >> 1, wn = wid & 1;
    const int qb = blockIdx.x;
    const int nb = blockIdx.y;

    const size_t qbase = (size_t)qb * BM * DIM;
    const size_t nbase = (size_t)nb * BN * DIM;

    if (tid < BN) vs[tid] = g_vsq[nb * BN + tid];

    const int r0a = tid >> 2, q0 = (tid & 3) * 8;
    const int r1a = (tid + 256) >> 2, q1 = ((tid + 256) & 3) * 8;

    uint32_t asA[2], asB[2], asA1[2], asB1[2];
#pragma unroll
    for (int s = 0; s < 2; s++) {
        asA[s]  = smem_u32(&As[s][r0a][q0]);
        asA1[s] = smem_u32(&As[s][r1a][q1]);
        asB[s]  = smem_u32(&Bs[s][r0a][q0]);
        asB1[s] = smem_u32(&Bs[s][r1a][q1]);
    }

#pragma unroll
    for (int c = 0; c < 2; c++) {
        const int c0 = c * BK;
        CP_ASYNC16(asA[c],  g_Qb + qbase + r0a * DIM + c0 + q0);
        CP_ASYNC16(asA1[c], g_Qb + qbase + r1a * DIM + c0 + q1);
        CP_ASYNC16(asB[c],  g_Vb + nbase + r0a * DIM + c0 + q0);
        CP_ASYNC16(asB1[c], g_Vb + nbase + r1a * DIM + c0 + q1);
        CP_COMMIT();
    }

    const int a_row = wm * 32 + ((lane >> 3) & 1) * 8 + (lane & 7);
    const int a_col = (lane >> 4) * 8;
    const int b_ni_off = (lane >> 4) & 1;
    const int b_kh = ((lane >> 3) & 1) * 8;
    const int b_r = lane & 7;

    float acc[2][8][4];
#pragma unroll
    for (int mi = 0; mi < 2; mi++)
#pragma unroll
        for (int ni = 0; ni < 8; ni++)
#pragma unroll
            for (int e = 0; e < 4; e++) acc[mi][ni][e] = 0.f;

#pragma unroll 1
    for (int c = 0; c < 8; c++) {
        if (c + 2 < 8) { CP_WAIT(1); } else { CP_WAIT(0); }
        __syncthreads();

        const int s = c & 1;
        const uint32_t aBase = smem_u32(&As[s][0][0]);
        const uint32_t bBase = smem_u32(&Bs[s][0][0]);

#pragma unroll
        for (int ks = 0; ks < BK; ks += 16) {
            uint32_t a[2][4];
#pragma unroll
            for (int mi = 0; mi < 2; mi++) {
                uint32_t addr = aBase + (uint32_t)((a_row + mi * 16) * 80 + (ks + a_col) * 2);
                ldsm_x4(a[mi][0], a[mi][1], a[mi][2], a[mi][3], addr);
            }
            uint32_t b[8][2];
#pragma unroll
            for (int p = 0; p < 8; p += 2) {
                int ni = p + b_ni_off;
                uint32_t addr = bBase + (uint32_t)((wn * 64 + ni * 8 + b_r) * 80 + (ks + b_kh) * 2);
                ldsm_x4(b[p][0], b[p][1], b[p + 1][0], b[p + 1][1], addr);
            }
#pragma unroll
            for (int mi = 0; mi < 2; mi++)
#pragma unroll
                for (int ni = 0; ni < 8; ni++)
                    mma16816(acc[mi][ni], a[mi], b[ni]);
        }
        __syncthreads();

        if (c + 2 < 8) {
            const int c0 = (c + 2) * BK;
            CP_ASYNC16(asA[s],  g_Qb + qbase + r0a * DIM + c0 + q0);
            CP_ASYNC16(asA1[s], g_Qb + qbase + r1a * DIM + c0 + q1);
            CP_ASYNC16(asB[s],  g_Vb + nbase + r0a * DIM + c0 + q0);
            CP_ASYNC16(asB1[s], g_Vb + nbase + r1a * DIM + c0 + q1);
            CP_COMMIT();
        }
    }

    const int gcol0 = nb * BN;
#pragma unroll
    for (int mi = 0; mi < 2; mi++) {
#pragma unroll
        for (int h = 0; h < 2; h++) {
            float v1 = 3.4e38f, v2 = 3.4e38f;
            int i1 = 0, i2 = 0;
#pragma unroll
            for (int ni = 0; ni < 8; ni++) {
                int c0 = wn * 64 + ni * 8 + tg * 2;
                float x0 = vs[c0]     - 2.0f * acc[mi][ni][h * 2];
                float x1 = vs[c0 + 1] - 2.0f * acc[mi][ni][h * 2 + 1];
                top2_upd(x0, gcol0 + c0,     v1, i1, v2, i2);
                top2_upd(x1, gcol0 + c0 + 1, v1, i1, v2, i2);
            }
            top2_shfl_merge(v1, i1, v2, i2, 1);
            top2_shfl_merge(v1, i1, v2, i2, 2);
            if (tg == 0) {
                int row = wm * 32 + mi * 16 + h * 8 + g;
                red[row][wn] = make_float4(v1, v2, __int_as_float(i1), __int_as_float(i2));
            }
        }
    }
    __syncthreads();

    if (tid < BM) {
        float4 e0 = red[tid][0];
        float4 e1 = red[tid][1];
        float v1, v2; int i1, i2;
        if (e0.x <= e1.x) {
            v1 = e0.x; i1 = __float_as_int(e0.z);
            if (e1.x < e0.y) { v2 = e1.x; i2 = __float_as_int(e1.z); }
            else             { v2 = e0.y; i2 = __float_as_int(e0.w); }
        } else {
            v1 = e1.x; i1 = __float_as_int(e1.z);
            if (e0.x < e1.y) { v2 = e0.x; i2 = __float_as_int(e0.z); }
            else             { v2 = e1.y; i2 = __float_as_int(e1.w); }
        }
        int q = qb * BM + tid;
        g_pv1[q * NBLK + nb] = v1;  g_pi1[q * NBLK + nb] = i1;
        g_pv2[q * NBLK + nb] = v2;  g_pi2[q * NBLK + nb] = i2;
    }
}

// ---------------------------------------------------------------------------
// refine: warp-per-query (unchanged)
// ---------------------------------------------------------------------------
__global__ void __launch_bounds__(256) refine_kernel(const float* __restrict__ query,
                                                     const float* __restrict__ vectors,
                                                     float* __restrict__ out) {
    const int lane = threadIdx.x & 31;
    const int m = blockIdx.x * 8 + (threadIdx.x >> 5);

    const float* qr = query + (size_t)m * DIM;
    float4 qa = *reinterpret_cast<const float4*>(qr + lane * 8);
    float4 qb = *reinterpret_cast<const float4*>(qr + lane * 8 + 4);

    const float4* p1 = reinterpret_cast<const float4*>(g_pv1 + (size_t)m * NBLK);
    float lm = 3.4e38f;
#pragma unroll
    for (int j = 0; j < 8; j++) {
        float4 v = p1[lane + 32 * j];
        lm = fminf(lm, fminf(fminf(v.x, v.y), fminf(v.z, v.w)));
    }
#pragma unroll
    for (int o = 16; o; o >>= 1) lm = fminf(lm, __shfl_xor_sync(0xFFFFFFFFu, lm, o));
    const float thresh = lm + MARGIN;

    float bestv = 3.4e38f;
    int   besti = 0x7fffffff;
    const float* r1 = g_pv1 + (size_t)m * NBLK;
    const float* r2 = g_pv2 + (size_t)m * NBLK;
#pragma unroll 1
    for (int e = lane; e < 2 * NBLK; e += 32) {
        float pv = (e < NBLK) ? r1[e] : r2[e - NBLK];
        unsigned bal = __ballot_sync(0xFFFFFFFFu, pv <= thresh);
        while (bal) {
            int src = __ffs(bal) - 1;
            bal &= bal - 1;
            int pe = __shfl_sync(0xFFFFFFFFu, e, src);
            int pi = (pe < NBLK) ? g_pi1[(size_t)m * NBLK + pe]
                                 : g_pi2[(size_t)m * NBLK + pe - NBLK];
            const float* vr = vectors + (size_t)pi * DIM;
            float4 va = *reinterpret_cast<const float4*>(vr + lane * 8);
            float4 vb = *reinterpret_cast<const float4*>(vr + lane * 8 + 4);
            float d0 = qa.x - va.x, d1 = qa.y - va.y, d2 = qa.z - va.z, d3 = qa.w - va.w;
            float e0 = qb.x - vb.x, e1 = qb.y - vb.y, e2 = qb.z - vb.z, e3 = qb.w - vb.w;
            float s = d0 * d0;
            s = fmaf(d1, d1, s); s = fmaf(d2, d2, s); s = fmaf(d3, d3, s);
            s = fmaf(e0, e0, s); s = fmaf(e1, e1, s); s = fmaf(e2, e2, s);
            s = fmaf(e3, e3, s);
#pragma unroll
            for (int o = 16; o; o >>= 1) s += __shfl_xor_sync(0xFFFFFFFFu, s, o);
            if (s < bestv || (s == bestv && pi < besti)) { bestv = s; besti = pi; }
        }
    }
    if (lane == 0) out[m] = (float)besti;
}

// ---------------------------------------------------------------------------
extern "C" void kernel_launch(void* const* d_in, const int* in_sizes, int n_in,
                              void* d_out, int out_size) {
    const float* query = nullptr;
    const float* vectors = nullptr;
    for (int i = 0; i < n_in; i++) {
        long long sz = in_sizes[i];
        if (sz == (long long)M_Q * DIM || sz == (long long)M_Q * DIM * 4) {
            if (!query) query = (const float*)d_in[i];
        } else if (sz == (long long)N_V * DIM || sz == (long long)N_V * DIM * 4) {
            if (!vectors) vectors = (const float*)d_in[i];
        }
    }
    if (!query)   query   = (const float*)d_in[0];
    if (!vectors) vectors = (const float*)d_in[1];

    float* out = (float*)d_out;

    cudaFuncSetAttribute(dist_tc_kernel, cudaFuncAttributeMaxDynamicSharedMemorySize, TG_SMEM);

    zero_flag_kernel<<<1, 1>>>();
    convert_vec_kernel<<<(N_V * 32) / 256, 256>>>(vectors);
    convert_q_kernel<<<(M_Q * 32) / 256, 256>>>(query);
    dist_tc_kernel<<<dim3(QBLK, NBLK2), 256, TG_SMEM>>>();
    dist_fb_kernel<<<dim3(QBLK, NBLK), 256>>>();
    refine_kernel<<<M_Q / 8, 256>>>(query, vectors, out);
}

// round 14
// speedup vs baseline: 1.2434x; 1.2434x over previous
#include <cuda_runtime.h>
#include <cuda_bf16.h>
#include <cstdint>

// ---------------------------------------------------------------------------
#define M_Q   2048
#define N_V   131072
#define DIM   256
#define BM    128
#define BN    128
#define BK    32
#define NBLK  (N_V / BN)          // 1024 partial blocks of 128 cols
#define QBLK  (M_Q / BM)          // 16
#define TPC   32                  // tiles per persistent tc CTA
#define GY    (NBLK / TPC)        // 32
#define MARGIN 3.0f

// tcgen05 legal only in arch/family-specific passes
#if defined(__CUDA_ARCH__) && ( \
      (defined(__CUDA_ARCH_SPECIFIC__)        && (__CUDA_ARCH_SPECIFIC__        >= 1000)) || \
      (defined(__CUDA_ARCH_FAMILY_SPECIFIC__) && (__CUDA_ARCH_FAMILY_SPECIFIC__ >= 1000)) || \
      defined(__CUDA_ARCH_FEAT_SM100_ALL) || defined(__CUDA_ARCH_FEAT_SM103_ALL))
#define TCG_PATH 1
#else
#define TCG_PATH 0
#endif

// ---------------------------------------------------------------------------
__device__ __nv_bfloat16 g_Vb[(size_t)N_V * DIM];
__device__ __nv_bfloat16 g_Qb[(size_t)M_Q * DIM];
__device__ float g_vsq[N_V];
__device__ float g_pv1[M_Q * NBLK];
__device__ float g_pv2[M_Q * NBLK];
__device__ int   g_pi1[M_Q * NBLK];
__device__ int   g_pi2[M_Q * NBLK];
__device__ int   g_tc_bad;

// ---------------------------------------------------------------------------
__device__ __forceinline__ uint32_t smem_u32(const void* p) {
    uint32_t a;
    asm("{ .reg .u64 t; cvta.to.shared.u64 t, %1; cvt.u32.u64 %0, t; }" : "=r"(a) : "l"(p));
    return a;
}

__global__ void zero_flag_kernel() { g_tc_bad = 0; }

// ---------------------------------------------------------------------------
// Convert kernels
// ---------------------------------------------------------------------------
__global__ void convert_vec_kernel(const float* __restrict__ src) {
    int warp = (blockIdx.x * blockDim.x + threadIdx.x) >> 5;
    int lane = threadIdx.x & 31;
    if (warp >= N_V) return;
    const float4* s = reinterpret_cast<const float4*>(src + (size_t)warp * DIM);
    uint2* d = reinterpret_cast<uint2*>(g_Vb + (size_t)warp * DIM);
    float acc = 0.f;
#pragma unroll
    for (int i = 0; i < 2; i++) {
        float4 f = s[lane + 32 * i];
        acc += f.x * f.x + f.y * f.y + f.z * f.z + f.w * f.w;
        __nv_bfloat162 lo = __floats2bfloat162_rn(f.x, f.y);
        __nv_bfloat162 hi = __floats2bfloat162_rn(f.z, f.w);
        uint2 u;
        u.x = *reinterpret_cast<uint32_t*>(&lo);
        u.y = *reinterpret_cast<uint32_t*>(&hi);
        d[lane + 32 * i] = u;
    }
#pragma unroll
    for (int o = 16; o; o >>= 1) acc += __shfl_xor_sync(0xFFFFFFFFu, acc, o);
    if (lane == 0) g_vsq[warp] = acc;
}

__global__ void convert_q_kernel(const float* __restrict__ src) {
    int warp = (blockIdx.x * blockDim.x + threadIdx.x) >> 5;
    int lane = threadIdx.x & 31;
    if (warp >= M_Q) return;
    const float4* s = reinterpret_cast<const float4*>(src + (size_t)warp * DIM);
    uint2* d = reinterpret_cast<uint2*>(g_Qb + (size_t)warp * DIM);
#pragma unroll
    for (int i = 0; i < 2; i++) {
        float4 f = s[lane + 32 * i];
        __nv_bfloat162 lo = __floats2bfloat162_rn(f.x, f.y);
        __nv_bfloat162 hi = __floats2bfloat162_rn(f.z, f.w);
        uint2 u;
        u.x = *reinterpret_cast<uint32_t*>(&lo);
        u.y = *reinterpret_cast<uint32_t*>(&hi);
        d[lane + 32 * i] = u;
    }
}

// ---------------------------------------------------------------------------
__device__ __forceinline__ void top2_upd(float v, int idx, float& v1, int& i1,
                                         float& v2, int& i2) {
    if (v < v1) { v2 = v1; i2 = i1; v1 = v; i1 = idx; }
    else if (v < v2) { v2 = v; i2 = idx; }
}

__device__ __forceinline__ void top2_shfl_merge(float& v1, int& i1, float& v2,
                                                int& i2, int m) {
    float ov1 = __shfl_xor_sync(0xFFFFFFFFu, v1, m);
    float ov2 = __shfl_xor_sync(0xFFFFFFFFu, v2, m);
    int   oi1 = __shfl_xor_sync(0xFFFFFFFFu, i1, m);
    int   oi2 = __shfl_xor_sync(0xFFFFFFFFu, i2, m);
    if (ov1 < v1) {
        if (v1 < ov2) { v2 = v1; i2 = i1; } else { v2 = ov2; i2 = oi2; }
        v1 = ov1; i1 = oi1;
    } else {
        if (ov1 < v2) { v2 = ov1; i2 = oi1; }
    }
}

// ---------------------------------------------------------------------------
#define CP_ASYNC16(dst, src) \
    asm volatile("cp.async.cg.shared.global [%0], [%1], 16;" :: "r"(dst), "l"(src))
#define CP_COMMIT() asm volatile("cp.async.commit_group;" ::: "memory")
#define CP_WAIT(n)  asm volatile("cp.async.wait_group %0;" :: "n"(n) : "memory")

// ---------------------------------------------------------------------------
// tcgen05 helpers
// ---------------------------------------------------------------------------
#if TCG_PATH
__device__ __forceinline__ uint32_t elect_one_pred() {
    uint32_t pred;
    asm volatile("{\n\t.reg .pred p;\n\telect.sync _|p, 0xFFFFFFFF;\n\tselp.b32 %0, 1, 0, p;\n\t}" : "=r"(pred));
    return pred;
}
#define TCGEN05_ALLOC(sm, n) \
    asm volatile("tcgen05.alloc.cta_group::1.sync.aligned.shared::cta.b32 [%0], %1;" :: "r"((uint32_t)(sm)), "r"((uint32_t)(n)) : "memory")
#define TCGEN05_DEALLOC(t, n) \
    asm volatile("tcgen05.dealloc.cta_group::1.sync.aligned.b32 %0, %1;" :: "r"(t), "r"((uint32_t)(n)))
#define TCGEN05_RELINQUISH() \
    asm volatile("tcgen05.relinquish_alloc_permit.cta_group::1.sync.aligned;")
#define TCGEN05_COMMIT(mb) \
    asm volatile("tcgen05.commit.cta_group::1.mbarrier::arrive::one.shared::cluster.b64 [%0];" :: "r"((uint32_t)(mb)) : "memory")
#define TCGEN05_FENCE_AFTER() \
    asm volatile("tcgen05.fence::after_thread_sync;" ::: "memory")
#define TCGEN05_FENCE_BEFORE() \
    asm volatile("tcgen05.fence::before_thread_sync;" ::: "memory")
#define TCGEN05_WAIT_LD() \
    asm volatile("tcgen05.wait::ld.sync.aligned;" ::: "memory")
#define MBARRIER_INIT(mb, cnt) \
    asm volatile("mbarrier.init.shared.b64 [%0], %1;" :: "r"((uint32_t)(mb)), "r"((uint32_t)(cnt)) : "memory")
#define FENCE_PROXY_ASYNC() \
    asm volatile("fence.proxy.async.shared::cta;" ::: "memory")

#define MBARRIER_WAIT_PARITY(mb, par) do {                                          \
    uint32_t _mb = (uint32_t)(mb); uint32_t _p = (uint32_t)(par); uint32_t _done;   \
    asm volatile("{\n\t.reg .pred p;\n\t"                                           \
        "mbarrier.try_wait.parity.acquire.cta.shared::cta.b64 p, [%1], %2;\n\t"     \
        "selp.b32 %0, 1, 0, p;\n\t}" : "=r"(_done) : "r"(_mb), "r"(_p) : "memory"); \
    if (!_done) {                                                                   \
        asm volatile("{\n\t.reg .pred P1;\n\t"                                      \
            "WL_%=:\n\t"                                                            \
            "mbarrier.try_wait.parity.acquire.cta.shared::cta.b64 P1, [%0], %1, 0x989680;\n\t" \
            "@P1 bra.uni WD_%=;\n\t"                                                \
            "bra.uni WL_%=;\n\t"                                                    \
            "WD_%=:\n\t}" :: "r"(_mb), "r"(_p) : "memory");                         \
    }                                                                               \
} while (0)

#define TCGEN05_LD_32X32B_X32(r, ta) \
    asm volatile( \
        "tcgen05.ld.sync.aligned.32x32b.x32.b32 " \
        "{%0, %1, %2, %3, %4, %5, %6, %7, " \
        " %8, %9, %10, %11, %12, %13, %14, %15, " \
        " %16, %17, %18, %19, %20, %21, %22, %23, " \
        " %24, %25, %26, %27, %28, %29, %30, %31}, [%32];" \
        : "=r"((r)[0]),  "=r"((r)[1]),  "=r"((r)[2]),  "=r"((r)[3]), \
          "=r"((r)[4]),  "=r"((r)[5]),  "=r"((r)[6]),  "=r"((r)[7]), \
          "=r"((r)[8]),  "=r"((r)[9]),  "=r"((r)[10]), "=r"((r)[11]), \
          "=r"((r)[12]), "=r"((r)[13]), "=r"((r)[14]), "=r"((r)[15]), \
          "=r"((r)[16]), "=r"((r)[17]), "=r"((r)[18]), "=r"((r)[19]), \
          "=r"((r)[20]), "=r"((r)[21]), "=r"((r)[22]), "=r"((r)[23]), \
          "=r"((r)[24]), "=r"((r)[25]), "=r"((r)[26]), "=r"((r)[27]), \
          "=r"((r)[28]), "=r"((r)[29]), "=r"((r)[30]), "=r"((r)[31]) \
        : "r"(ta))

static constexpr uint64_t SMEM_DESC_BASE_SW128 =
    (uint64_t(2) << 61) | (uint64_t(1) << 46) | (uint64_t(64) << 32) | (uint64_t(1) << 16);
#define MAKE_SMEM_DESC(a) (SMEM_DESC_BASE_SW128 | ((uint64_t)((a) >> 4) & 0x3FFF))
#define SW128(b) ((b) ^ (((b) >> 3) & 0x70))

__device__ __forceinline__ void mma_bf16_ss(uint32_t d_tmem, uint64_t a_desc,
                                            uint64_t b_desc, uint32_t idesc,
                                            uint32_t enable) {
    asm volatile(
        "{\n\t.reg .pred p;\n\t"
        "setp.ne.u32 p, %4, 0;\n\t"
        "tcgen05.mma.cta_group::1.kind::f16 [%0], %1, %2, %3, {%5, %5, %5, %5}, p;\n\t"
        "}"
        :: "r"(d_tmem), "l"(a_desc), "l"(b_desc), "r"(idesc), "r"(enable), "r"(0u)
        : "memory");
}

// idesc: dtype=F32, atype=BF16, btype=BF16, N=128, M=128
static constexpr uint32_t MMA_IDESC =
    (1u << 4) | (1u << 7) | (1u << 10) | ((BN / 8) << 17) | ((BM / 16) << 24);
#endif  // TCG_PATH

// ---------------------------------------------------------------------------
// HMMA helpers (fallback)
// ---------------------------------------------------------------------------
__device__ __forceinline__ void mma16816(float* c, const uint32_t* a, const uint32_t* b) {
    asm volatile(
        "mma.sync.aligned.m16n8k16.row.col.f32.bf16.bf16.f32 "
        "{%0,%1,%2,%3}, {%4,%5,%6,%7}, {%8,%9}, {%0,%1,%2,%3};"
        : "+f"(c[0]), "+f"(c[1]), "+f"(c[2]), "+f"(c[3])
        : "r"(a[0]), "r"(a[1]), "r"(a[2]), "r"(a[3]), "r"(b[0]), "r"(b[1]));
}

__device__ __forceinline__ void ldsm_x4(uint32_t& r0, uint32_t& r1, uint32_t& r2,
                                        uint32_t& r3, uint32_t addr) {
    asm volatile("ldmatrix.sync.aligned.m8n8.x4.shared.b16 {%0,%1,%2,%3}, [%4];"
                 : "=r"(r0), "=r"(r1), "=r"(r2), "=r"(r3) : "r"(addr));
}

// ---------------------------------------------------------------------------
// dist_tc: persistent pipelined tcgen05. grid (16, 32), 256 thr, 1 CTA/SM.
// A (128x256) stationary; 32 B tiles (128x256) double-buffered cp.async;
// D double-buffered in TMEM (cols 0-127 / 128-255).
// SMEM map: [0]tmem [8]mb0 [16]mb1 [24]ref, vs[4][128]@32,
//           A@4096 (64KB), B0@69632, B1@135168, red@200704 (4KB) = 204800.
// ---------------------------------------------------------------------------
#define P_VS   32
#define P_A    4096
#define P_B0   69632
#define P_B1   135168
#define P_RED  200704
#define TG_SMEM 204800

__global__ void __launch_bounds__(256, 1) dist_tc_kernel() {
#if TCG_PATH
    extern __shared__ char smem[];
    uint32_t sb = smem_u32(smem);
    const int tid = threadIdx.x;
    const int wid = tid >> 5;
    const int lane = tid & 31;
    const int qb = blockIdx.x;
    const int nb0 = blockIdx.y * TPC;

    if (wid == 0) {
        TCGEN05_ALLOC(sb + 0, 256);
        TCGEN05_RELINQUISH();
    }
    if (tid == 0) { MBARRIER_INIT(sb + 8, 1); MBARRIER_INIT(sb + 16, 1); }
    __syncthreads();
    uint32_t tmem;
    asm volatile("ld.shared.b32 %0, [%1];" : "=r"(tmem) : "r"(sb + 0));

    float* vs4 = reinterpret_cast<float*>(smem + P_VS);   // [4][128]
    float4* red = reinterpret_cast<float4*>(smem + P_RED); // [128][2]

    // Per-thread tile-unit mapping (4096 16B units; 16 per thread)
    // unit u: row = u>>5, cu = u&31; swizzled atom layout (16 atom-rows x 4 cols)
    uint32_t swoff[16];
#pragma unroll
    for (int i = 0; i < 16; i++) {
        int u = tid + 256 * i;
        int row = u >> 5, cu = u & 31;
        int ac = cu >> 3, iu = cu & 7;
        int ar = row >> 3, ir = row & 7;
        uint32_t byt = ((uint32_t)(ac * 16 + ar) << 10) + (ir << 7) + (iu << 4);
        swoff[i] = SW128(byt);
    }

    // ---- Load stationary A tile (plain LDG/STS, once) ----
    {
        const uint4* src = reinterpret_cast<const uint4*>(g_Qb + (size_t)qb * BM * DIM);
#pragma unroll
        for (int i = 0; i < 16; i++) {
            int u = tid + 256 * i;
            *reinterpret_cast<uint4*>(smem + P_A + swoff[i]) = src[u];
        }
    }

    // ---- Prologue: cp.async B tile 0 -> B0; vsq tile 0 ----
    {
        const char* src = reinterpret_cast<const char*>(g_Vb + (size_t)nb0 * BN * DIM);
#pragma unroll
        for (int i = 0; i < 16; i++) {
            int u = tid + 256 * i;
            CP_ASYNC16(sb + P_B0 + swoff[i], src + u * 16);
        }
        if (tid < BN) vs4[tid] = g_vsq[nb0 * BN + tid];
        CP_COMMIT();
    }

    const uint64_t ad = MAKE_SMEM_DESC(sb + P_A);
    const uint64_t bd0 = MAKE_SMEM_DESC(sb + P_B0);
    const uint64_t bd1 = MAKE_SMEM_DESC(sb + P_B1);

    int ph0 = 0, ph1 = 0;

#pragma unroll 1
    for (int t = 0; t < TPC; t++) {
        const int s = t & 1;

        CP_WAIT(0);
        FENCE_PROXY_ASYNC();
        __syncthreads();

        // Tile-0 reference dot (A row0 . B row0, bf16 exact) for validation
        if (t == 0 && wid == 0) {
            float ref = 0.f;
#pragma unroll
            for (int t8 = 0; t8 < 8; t8++) {
                int k = lane * 8 + t8;
                uint32_t off = ((uint32_t)(k >> 6) << 14) + (uint32_t)(k & 63) * 2;
                float a = __bfloat162float(*reinterpret_cast<const __nv_bfloat16*>(smem + P_A + off));
                float b = __bfloat162float(*reinterpret_cast<const __nv_bfloat16*>(smem + P_B0 + off));
                ref += a * b;
            }
#pragma unroll
            for (int o = 16; o; o >>= 1) ref += __shfl_xor_sync(0xFFFFFFFFu, ref, o);
            if (lane == 0) *reinterpret_cast<float*>(smem + 24) = ref;
        }

        // Issue MMA(t) -> D[s]
        if (wid == 0) {
            TCGEN05_FENCE_AFTER();
            const uint64_t bd = s ? bd1 : bd0;
            if (elect_one_pred()) {
#pragma unroll
                for (int k = 0; k < 16; k++) {
                    uint64_t off = (uint64_t)((k >> 2) * 1024 + (k & 3) * 2);
                    mma_bf16_ss(tmem + s * 128, ad + off, bd + off, MMA_IDESC,
                                (uint32_t)(k > 0));
                }
                TCGEN05_COMMIT(sb + (s ? 16 : 8));
            }
        }

        // Epilogue(t-1) from D[1-s]; then issue B load for tile t+1 into B[1-s]
        if (t > 0) {
            const int sd = 1 - s;
            if (sd) { MBARRIER_WAIT_PARITY(sb + 16, ph1); ph1 ^= 1; }
            else    { MBARRIER_WAIT_PARITY(sb + 8,  ph0); ph0 ^= 1; }
            TCGEN05_FENCE_AFTER();

            const int tp = t - 1;
            const int half = wid >> 2;
            const float* vst = vs4 + (tp & 3) * BN;
            float v1 = 3.4e38f, v2 = 3.4e38f;
            int i1 = 0, i2 = 0;
            uint32_t r[32];
#pragma unroll 1
            for (int b = 0; b < 2; b++) {
                TCGEN05_LD_32X32B_X32(r, tmem + sd * 128 + half * 64 + b * 32);
                TCGEN05_WAIT_LD();
                if (tp == 0 && b == 0 && wid == 0 && lane == 0) {
                    float ref = *reinterpret_cast<float*>(smem + 24);
                    float d00 = __uint_as_float(r[0]);
                    if (!(fabsf(d00 - ref) <= 0.5f)) atomicOr(&g_tc_bad, 1);
                }
#pragma unroll
                for (int j = 0; j < 32; j++) {
                    int col = half * 64 + b * 32 + j;
                    float val = vst[col] - 2.0f * __uint_as_float(r[j]);
                    top2_upd(val, (nb0 + tp) * BN + col, v1, i1, v2, i2);
                }
            }
            int row = (wid & 3) * 32 + lane;
            red[row * 2 + half] = make_float4(v1, v2, __int_as_float(i1), __int_as_float(i2));

            // issue next B tile (t+1) into B[1-s] (safe: MMA(t-1) complete)
            if (t + 1 < TPC) {
                const char* src = reinterpret_cast<const char*>(
                    g_Vb + (size_t)(nb0 + t + 1) * BN * DIM);
                uint32_t base = sb + (sd ? P_B1 : P_B0);
#pragma unroll
                for (int i = 0; i < 16; i++) {
                    int u = tid + 256 * i;
                    CP_ASYNC16(base + swoff[i], src + u * 16);
                }
                if (tid < BN) vs4[((t + 1) & 3) * BN + tid] = g_vsq[(nb0 + t + 1) * BN + tid];
                CP_COMMIT();
            }

            __syncthreads();
            if (tid < BM) {
                float4 e0 = red[tid * 2 + 0];
                float4 e1 = red[tid * 2 + 1];
                float w1, w2; int j1, j2;
                if (e0.x <= e1.x) {
                    w1 = e0.x; j1 = __float_as_int(e0.z);
                    if (e1.x < e0.y) { w2 = e1.x; j2 = __float_as_int(e1.z); }
                    else             { w2 = e0.y; j2 = __float_as_int(e0.w); }
                } else {
                    w1 = e1.x; j1 = __float_as_int(e1.z);
                    if (e0.x < e1.y) { w2 = e0.x; j2 = __float_as_int(e0.z); }
                    else             { w2 = e1.y; j2 = __float_as_int(e1.w); }
                }
                int q = qb * BM + tid;
                int pb = nb0 + tp;
                g_pv1[q * NBLK + pb] = w1;  g_pi1[q * NBLK + pb] = j1;
                g_pv2[q * NBLK + pb] = w2;  g_pi2[q * NBLK + pb] = j2;
            }
        } else {
            // t == 0: issue tile 1 into B1 (untouched buffer)
            const char* src = reinterpret_cast<const char*>(
                g_Vb + (size_t)(nb0 + 1) * BN * DIM);
#pragma unroll
            for (int i = 0; i < 16; i++) {
                int u = tid + 256 * i;
                CP_ASYNC16(sb + P_B1 + swoff[i], src + u * 16);
            }
            if (tid < BN) vs4[BN + tid] = g_vsq[(nb0 + 1) * BN + tid];
            CP_COMMIT();
        }
    }

    // ---- Tail epilogue: tile TPC-1 from D[(TPC-1)&1] ----
    {
        const int tp = TPC - 1;
        const int sd = tp & 1;
        if (sd) { MBARRIER_WAIT_PARITY(sb + 16, ph1); ph1 ^= 1; }
        else    { MBARRIER_WAIT_PARITY(sb + 8,  ph0); ph0 ^= 1; }
        TCGEN05_FENCE_AFTER();

        const int half = wid >> 2;
        const float* vst = vs4 + (tp & 3) * BN;
        float v1 = 3.4e38f, v2 = 3.4e38f;
        int i1 = 0, i2 = 0;
        uint32_t r[32];
#pragma unroll 1
        for (int b = 0; b < 2; b++) {
            TCGEN05_LD_32X32B_X32(r, tmem + sd * 128 + half * 64 + b * 32);
            TCGEN05_WAIT_LD();
#pragma unroll
            for (int j = 0; j < 32; j++) {
                int col = half * 64 + b * 32 + j;
                float val = vst[col] - 2.0f * __uint_as_float(r[j]);
                top2_upd(val, (nb0 + tp) * BN + col, v1, i1, v2, i2);
            }
        }
        int row = (wid & 3) * 32 + lane;
        red[row * 2 + half] = make_float4(v1, v2, __int_as_float(i1), __int_as_float(i2));
        __syncthreads();
        if (tid < BM) {
            float4 e0 = red[tid * 2 + 0];
            float4 e1 = red[tid * 2 + 1];
            float w1, w2; int j1, j2;
            if (e0.x <= e1.x) {
                w1 = e0.x; j1 = __float_as_int(e0.z);
                if (e1.x < e0.y) { w2 = e1.x; j2 = __float_as_int(e1.z); }
                else             { w2 = e0.y; j2 = __float_as_int(e0.w); }
            } else {
                w1 = e1.x; j1 = __float_as_int(e1.z);
                if (e0.x < e1.y) { w2 = e0.x; j2 = __float_as_int(e0.z); }
                else             { w2 = e1.y; j2 = __float_as_int(e1.w); }
            }
            int q = qb * BM + tid;
            int pb = nb0 + tp;
            g_pv1[q * NBLK + pb] = w1;  g_pi1[q * NBLK + pb] = j1;
            g_pv2[q * NBLK + pb] = w2;  g_pi2[q * NBLK + pb] = j2;
        }
    }
    __syncthreads();
    if (wid == 0) TCGEN05_DEALLOC(tmem, 256);
#else
    if (threadIdx.x == 0 && blockIdx.x == 0 && blockIdx.y == 0) g_tc_bad = 1;
#endif
}

// ---------------------------------------------------------------------------
// dist_fb: proven HMMA kernel; runs only if tcgen05 invalid.
// ---------------------------------------------------------------------------
__global__ void __launch_bounds__(256, 2) dist_fb_kernel() {
    if (*(volatile int*)&g_tc_bad == 0) return;

    __shared__ __nv_bfloat16 As[2][BM][40];
    __shared__ __nv_bfloat16 Bs[2][BN][40];
    __shared__ float vs[BN];
    __shared__ float4 red[BM][2];

    const int tid = threadIdx.x;
    const int wid = tid >> 5;
    const int lane = tid & 31;
    const int g = lane >> 2, tg = lane & 3;
    const int wm = wid >> 1, wn = wid & 1;
    const int qb = blockIdx.x;
    const int nb = blockIdx.y;

    const size_t qbase = (size_t)qb * BM * DIM;
    const size_t nbase = (size_t)nb * BN * DIM;

    if (tid < BN) vs[tid] = g_vsq[nb * BN + tid];

    const int r0a = tid >> 2, q0 = (tid & 3) * 8;
    const int r1a = (tid + 256) >> 2, q1 = ((tid + 256) & 3) * 8;

    uint32_t asA[2], asB[2], asA1[2], asB1[2];
#pragma unroll
    for (int s = 0; s < 2; s++) {
        asA[s]  = smem_u32(&As[s][r0a][q0]);
        asA1[s] = smem_u32(&As[s][r1a][q1]);
        asB[s]  = smem_u32(&Bs[s][r0a][q0]);
        asB1[s] = smem_u32(&Bs[s][r1a][q1]);
    }

#pragma unroll
    for (int c = 0; c < 2; c++) {
        const int c0 = c * BK;
        CP_ASYNC16(asA[c],  g_Qb + qbase + r0a * DIM + c0 + q0);
        CP_ASYNC16(asA1[c], g_Qb + qbase + r1a * DIM + c0 + q1);
        CP_ASYNC16(asB[c],  g_Vb + nbase + r0a * DIM + c0 + q0);
        CP_ASYNC16(asB1[c], g_Vb + nbase + r1a * DIM + c0 + q1);
        CP_COMMIT();
    }

    const int a_row = wm * 32 + ((lane >> 3) & 1) * 8 + (lane & 7);
    const int a_col = (lane >> 4) * 8;
    const int b_ni_off = (lane >> 4) & 1;
    const int b_kh = ((lane >> 3) & 1) * 8;
    const int b_r = lane & 7;

    float acc[2][8][4];
#pragma unroll
    for (int mi = 0; mi < 2; mi++)
#pragma unroll
        for (int ni = 0; ni < 8; ni++)
#pragma unroll
            for (int e = 0; e < 4; e++) acc[mi][ni][e] = 0.f;

#pragma unroll 1
    for (int c = 0; c < 8; c++) {
        if (c + 2 < 8) { CP_WAIT(1); } else { CP_WAIT(0); }
        __syncthreads();

        const int s = c & 1;
        const uint32_t aBase = smem_u32(&As[s][0][0]);
        const uint32_t bBase = smem_u32(&Bs[s][0][0]);

#pragma unroll
        for (int ks = 0; ks < BK; ks += 16) {
            uint32_t a[2][4];
#pragma unroll
            for (int mi = 0; mi < 2; mi++) {
                uint32_t addr = aBase + (uint32_t)((a_row + mi * 16) * 80 + (ks + a_col) * 2);
                ldsm_x4(a[mi][0], a[mi][1], a[mi][2], a[mi][3], addr);
            }
            uint32_t b[8][2];
#pragma unroll
            for (int p = 0; p < 8; p += 2) {
                int ni = p + b_ni_off;
                uint32_t addr = bBase + (uint32_t)((wn * 64 + ni * 8 + b_r) * 80 + (ks + b_kh) * 2);
                ldsm_x4(b[p][0], b[p][1], b[p + 1][0], b[p + 1][1], addr);
            }
#pragma unroll
            for (int mi = 0; mi < 2; mi++)
#pragma unroll
                for (int ni = 0; ni < 8; ni++)
                    mma16816(acc[mi][ni], a[mi], b[ni]);
        }
        __syncthreads();

        if (c + 2 < 8) {
            const int c0 = (c + 2) * BK;
            CP_ASYNC16(asA[s],  g_Qb + qbase + r0a * DIM + c0 + q0);
            CP_ASYNC16(asA1[s], g_Qb + qbase + r1a * DIM + c0 + q1);
            CP_ASYNC16(asB[s],  g_Vb + nbase + r0a * DIM + c0 + q0);
            CP_ASYNC16(asB1[s], g_Vb + nbase + r1a * DIM + c0 + q1);
            CP_COMMIT();
        }
    }

    const int gcol0 = nb * BN;
#pragma unroll
    for (int mi = 0; mi < 2; mi++) {
#pragma unroll
        for (int h = 0; h < 2; h++) {
            float v1 = 3.4e38f, v2 = 3.4e38f;
            int i1 = 0, i2 = 0;
#pragma unroll
            for (int ni = 0; ni < 8; ni++) {
                int c0 = wn * 64 + ni * 8 + tg * 2;
                float x0 = vs[c0]     - 2.0f * acc[mi][ni][h * 2];
                float x1 = vs[c0 + 1] - 2.0f * acc[mi][ni][h * 2 + 1];
                top2_upd(x0, gcol0 + c0,     v1, i1, v2, i2);
                top2_upd(x1, gcol0 + c0 + 1, v1, i1, v2, i2);
            }
            top2_shfl_merge(v1, i1, v2, i2, 1);
            top2_shfl_merge(v1, i1, v2, i2, 2);
            if (tg == 0) {
                int row = wm * 32 + mi * 16 + h * 8 + g;
                red[row][wn] = make_float4(v1, v2, __int_as_float(i1), __int_as_float(i2));
            }
        }
    }
    __syncthreads();

    if (tid < BM) {
        float4 e0 = red[tid][0];
        float4 e1 = red[tid][1];
        float v1, v2; int i1, i2;
        if (e0.x <= e1.x) {
            v1 = e0.x; i1 = __float_as_int(e0.z);
            if (e1.x < e0.y) { v2 = e1.x; i2 = __float_as_int(e1.z); }
            else             { v2 = e0.y; i2 = __float_as_int(e0.w); }
        } else {
            v1 = e1.x; i1 = __float_as_int(e1.z);
            if (e0.x < e1.y) { v2 = e0.x; i2 = __float_as_int(e0.z); }
            else             { v2 = e1.y; i2 = __float_as_int(e1.w); }
        }
        int q = qb * BM + tid;
        g_pv1[q * NBLK + nb] = v1;  g_pi1[q * NBLK + nb] = i1;
        g_pv2[q * NBLK + nb] = v2;  g_pi2[q * NBLK + nb] = i2;
    }
}

// ---------------------------------------------------------------------------
// refine: warp-per-query (unchanged)
// ---------------------------------------------------------------------------
__global__ void __launch_bounds__(256) refine_kernel(const float* __restrict__ query,
                                                     const float* __restrict__ vectors,
                                                     float* __restrict__ out) {
    const int lane = threadIdx.x & 31;
    const int m = blockIdx.x * 8 + (threadIdx.x >> 5);

    const float* qr = query + (size_t)m * DIM;
    float4 qa = *reinterpret_cast<const float4*>(qr + lane * 8);
    float4 qb = *reinterpret_cast<const float4*>(qr + lane * 8 + 4);

    const float4* p1 = reinterpret_cast<const float4*>(g_pv1 + (size_t)m * NBLK);
    float lm = 3.4e38f;
#pragma unroll
    for (int j = 0; j < 8; j++) {
        float4 v = p1[lane + 32 * j];
        lm = fminf(lm, fminf(fminf(v.x, v.y), fminf(v.z, v.w)));
    }
#pragma unroll
    for (int o = 16; o; o >>= 1) lm = fminf(lm, __shfl_xor_sync(0xFFFFFFFFu, lm, o));
    const float thresh = lm + MARGIN;

    float bestv = 3.4e38f;
    int   besti = 0x7fffffff;
    const float* r1 = g_pv1 + (size_t)m * NBLK;
    const float* r2 = g_pv2 + (size_t)m * NBLK;
#pragma unroll 1
    for (int e = lane; e < 2 * NBLK; e += 32) {
        float pv = (e < NBLK) ? r1[e] : r2[e - NBLK];
        unsigned bal = __ballot_sync(0xFFFFFFFFu, pv <= thresh);
        while (bal) {
            int src = __ffs(bal) - 1;
            bal &= bal - 1;
            int pe = __shfl_sync(0xFFFFFFFFu, e, src);
            int pi = (pe < NBLK) ? g_pi1[(size_t)m * NBLK + pe]
                                 : g_pi2[(size_t)m * NBLK + pe - NBLK];
            const float* vr = vectors + (size_t)pi * DIM;
            float4 va = *reinterpret_cast<const float4*>(vr + lane * 8);
            float4 vb = *reinterpret_cast<const float4*>(vr + lane * 8 + 4);
            float d0 = qa.x - va.x, d1 = qa.y - va.y, d2 = qa.z - va.z, d3 = qa.w - va.w;
            float e0 = qb.x - vb.x, e1 = qb.y - vb.y, e2 = qb.z - vb.z, e3 = qb.w - vb.w;
            float s = d0 * d0;
            s = fmaf(d1, d1, s); s = fmaf(d2, d2, s); s = fmaf(d3, d3, s);
            s = fmaf(e0, e0, s); s = fmaf(e1, e1, s); s = fmaf(e2, e2, s);
            s = fmaf(e3, e3, s);
#pragma unroll
            for (int o = 16; o; o >>= 1) s += __shfl_xor_sync(0xFFFFFFFFu, s, o);
            if (s < bestv || (s == bestv && pi < besti)) { bestv = s; besti = pi; }
        }
    }
    if (lane == 0) out[m] = (float)besti;
}

// ---------------------------------------------------------------------------
extern "C" void kernel_launch(void* const* d_in, const int* in_sizes, int n_in,
                              void* d_out, int out_size) {
    const float* query = nullptr;
    const float* vectors = nullptr;
    for (int i = 0; i < n_in; i++) {
        long long sz = in_sizes[i];
        if (sz == (long long)M_Q * DIM || sz == (long long)M_Q * DIM * 4) {
            if (!query) query = (const float*)d_in[i];
        } else if (sz == (long long)N_V * DIM || sz == (long long)N_V * DIM * 4) {
            if (!vectors) vectors = (const float*)d_in[i];
        }
    }
    if (!query)   query   = (const float*)d_in[0];
    if (!vectors) vectors = (const float*)d_in[1];

    float* out = (float*)d_out;

    cudaFuncSetAttribute(dist_tc_kernel, cudaFuncAttributeMaxDynamicSharedMemorySize, TG_SMEM);

    zero_flag_kernel<<<1, 1>>>();
    convert_vec_kernel<<<(N_V * 32) / 256, 256>>>(vectors);
    convert_q_kernel<<<(M_Q * 32) / 256, 256>>>(query);
    dist_tc_kernel<<<dim3(QBLK, GY), 256, TG_SMEM>>>();
    dist_fb_kernel<<<dim3(QBLK, NBLK), 256>>>();
    refine_kernel<<<M_Q / 8, 256>>>(query, vectors, out);
}

// round 16
// speedup vs baseline: 1.3798x; 1.1097x over previous
#include <cuda_runtime.h>
#include <cuda_bf16.h>
#include <cstdint>

// Round 16 = round 15 resubmission (container infra failure, kernel untested).
// ---------------------------------------------------------------------------
#define M_Q   2048
#define N_V   131072
#define DIM   256
#define BM    128
#define BN    128
#define BK    32
#define NBLK  (N_V / BN)          // 1024 partial blocks of 128 cols
#define QBLK  (M_Q / BM)          // 16
#define TPC   32                  // tiles per persistent tc CTA
#define GY    (NBLK / TPC)        // 32
#define NT    512                 // threads in tc kernel
#define MARGIN 3.0f

// tcgen05 legal only in arch/family-specific passes
#if defined(__CUDA_ARCH__) && ( \
      (defined(__CUDA_ARCH_SPECIFIC__)        && (__CUDA_ARCH_SPECIFIC__        >= 1000)) || \
      (defined(__CUDA_ARCH_FAMILY_SPECIFIC__) && (__CUDA_ARCH_FAMILY_SPECIFIC__ >= 1000)) || \
      defined(__CUDA_ARCH_FEAT_SM100_ALL) || defined(__CUDA_ARCH_FEAT_SM103_ALL))
#define TCG_PATH 1
#else
#define TCG_PATH 0
#endif

// ---------------------------------------------------------------------------
__device__ __nv_bfloat16 g_Vb[(size_t)N_V * DIM];
__device__ __nv_bfloat16 g_Qb[(size_t)M_Q * DIM];
__device__ float g_vsq[N_V];
__device__ float g_pv1[M_Q * NBLK];
__device__ float g_pv2[M_Q * NBLK];
__device__ int   g_pi1[M_Q * NBLK];
__device__ int   g_pi2[M_Q * NBLK];
__device__ int   g_tc_bad;

// ---------------------------------------------------------------------------
__device__ __forceinline__ uint32_t smem_u32(const void* p) {
    uint32_t a;
    asm("{ .reg .u64 t; cvta.to.shared.u64 t, %1; cvt.u32.u64 %0, t; }" : "=r"(a) : "l"(p));
    return a;
}

__global__ void zero_flag_kernel() { g_tc_bad = 0; }

// ---------------------------------------------------------------------------
// Convert kernels
// ---------------------------------------------------------------------------
__global__ void convert_vec_kernel(const float* __restrict__ src) {
    int warp = (blockIdx.x * blockDim.x + threadIdx.x) >> 5;
    int lane = threadIdx.x & 31;
    if (warp >= N_V) return;
    const float4* s = reinterpret_cast<const float4*>(src + (size_t)warp * DIM);
    uint2* d = reinterpret_cast<uint2*>(g_Vb + (size_t)warp * DIM);
    float acc = 0.f;
#pragma unroll
    for (int i = 0; i < 2; i++) {
        float4 f = s[lane + 32 * i];
        acc += f.x * f.x + f.y * f.y + f.z * f.z + f.w * f.w;
        __nv_bfloat162 lo = __floats2bfloat162_rn(f.x, f.y);
        __nv_bfloat162 hi = __floats2bfloat162_rn(f.z, f.w);
        uint2 u;
        u.x = *reinterpret_cast<uint32_t*>(&lo);
        u.y = *reinterpret_cast<uint32_t*>(&hi);
        d[lane + 32 * i] = u;
    }
#pragma unroll
    for (int o = 16; o; o >>= 1) acc += __shfl_xor_sync(0xFFFFFFFFu, acc, o);
    if (lane == 0) g_vsq[warp] = acc;
}

__global__ void convert_q_kernel(const float* __restrict__ src) {
    int warp = (blockIdx.x * blockDim.x + threadIdx.x) >> 5;
    int lane = threadIdx.x & 31;
    if (warp >= M_Q) return;
    const float4* s = reinterpret_cast<const float4*>(src + (size_t)warp * DIM);
    uint2* d = reinterpret_cast<uint2*>(g_Qb + (size_t)warp * DIM);
#pragma unroll
    for (int i = 0; i < 2; i++) {
        float4 f = s[lane + 32 * i];
        __nv_bfloat162 lo = __floats2bfloat162_rn(f.x, f.y);
        __nv_bfloat162 hi = __floats2bfloat162_rn(f.z, f.w);
        uint2 u;
        u.x = *reinterpret_cast<uint32_t*>(&lo);
        u.y = *reinterpret_cast<uint32_t*>(&hi);
        d[lane + 32 * i] = u;
    }
}

// ---------------------------------------------------------------------------
__device__ __forceinline__ void top2_upd(float v, int idx, float& v1, int& i1,
                                         float& v2, int& i2) {
    if (v < v1) { v2 = v1; i2 = i1; v1 = v; i1 = idx; }
    else if (v < v2) { v2 = v; i2 = idx; }
}

__device__ __forceinline__ void pair_merge(float& v1, int& i1, float& v2, int& i2,
                                           float w1, int j1, float w2, int j2) {
    if (w1 < v1) {
        float nv2; int ni2;
        if (v1 < w2) { nv2 = v1; ni2 = i1; } else { nv2 = w2; ni2 = j2; }
        v2 = nv2; i2 = ni2; v1 = w1; i1 = j1;
    } else if (w1 < v2) {
        v2 = w1; i2 = j1;
    }
}

__device__ __forceinline__ void top2_shfl_merge(float& v1, int& i1, float& v2,
                                                int& i2, int m) {
    float ov1 = __shfl_xor_sync(0xFFFFFFFFu, v1, m);
    float ov2 = __shfl_xor_sync(0xFFFFFFFFu, v2, m);
    int   oi1 = __shfl_xor_sync(0xFFFFFFFFu, i1, m);
    int   oi2 = __shfl_xor_sync(0xFFFFFFFFu, i2, m);
    pair_merge(v1, i1, v2, i2, ov1, oi1, ov2, oi2);
}

// ---------------------------------------------------------------------------
#define CP_ASYNC16(dst, src) \
    asm volatile("cp.async.cg.shared.global [%0], [%1], 16;" :: "r"(dst), "l"(src))
#define CP_COMMIT() asm volatile("cp.async.commit_group;" ::: "memory")
#define CP_WAIT(n)  asm volatile("cp.async.wait_group %0;" :: "n"(n) : "memory")

// ---------------------------------------------------------------------------
// tcgen05 helpers
// ---------------------------------------------------------------------------
#if TCG_PATH
__device__ __forceinline__ uint32_t elect_one_pred() {
    uint32_t pred;
    asm volatile("{\n\t.reg .pred p;\n\telect.sync _|p, 0xFFFFFFFF;\n\tselp.b32 %0, 1, 0, p;\n\t}" : "=r"(pred));
    return pred;
}
#define TCGEN05_ALLOC(sm, n) \
    asm volatile("tcgen05.alloc.cta_group::1.sync.aligned.shared::cta.b32 [%0], %1;" :: "r"((uint32_t)(sm)), "r"((uint32_t)(n)) : "memory")
#define TCGEN05_DEALLOC(t, n) \
    asm volatile("tcgen05.dealloc.cta_group::1.sync.aligned.b32 %0, %1;" :: "r"(t), "r"((uint32_t)(n)))
#define TCGEN05_RELINQUISH() \
    asm volatile("tcgen05.relinquish_alloc_permit.cta_group::1.sync.aligned;")
#define TCGEN05_COMMIT(mb) \
    asm volatile("tcgen05.commit.cta_group::1.mbarrier::arrive::one.shared::cluster.b64 [%0];" :: "r"((uint32_t)(mb)) : "memory")
#define TCGEN05_FENCE_AFTER() \
    asm volatile("tcgen05.fence::after_thread_sync;" ::: "memory")
#define TCGEN05_FENCE_BEFORE() \
    asm volatile("tcgen05.fence::before_thread_sync;" ::: "memory")
#define TCGEN05_WAIT_LD() \
    asm volatile("tcgen05.wait::ld.sync.aligned;" ::: "memory")
#define MBARRIER_INIT(mb, cnt) \
    asm volatile("mbarrier.init.shared.b64 [%0], %1;" :: "r"((uint32_t)(mb)), "r"((uint32_t)(cnt)) : "memory")
#define FENCE_PROXY_ASYNC() \
    asm volatile("fence.proxy.async.shared::cta;" ::: "memory")

#define MBARRIER_WAIT_PARITY(mb, par) do {                                          \
    uint32_t _mb = (uint32_t)(mb); uint32_t _p = (uint32_t)(par); uint32_t _done;   \
    asm volatile("{\n\t.reg .pred p;\n\t"                                           \
        "mbarrier.try_wait.parity.acquire.cta.shared::cta.b64 p, [%1], %2;\n\t"     \
        "selp.b32 %0, 1, 0, p;\n\t}" : "=r"(_done) : "r"(_mb), "r"(_p) : "memory"); \
    if (!_done) {                                                                   \
        asm volatile("{\n\t.reg .pred P1;\n\t"                                      \
            "WL_%=:\n\t"                                                            \
            "mbarrier.try_wait.parity.acquire.cta.shared::cta.b64 P1, [%0], %1, 0x989680;\n\t" \
            "@P1 bra.uni WD_%=;\n\t"                                                \
            "bra.uni WL_%=;\n\t"                                                    \
            "WD_%=:\n\t}" :: "r"(_mb), "r"(_p) : "memory");                         \
    }                                                                               \
} while (0)

#define TCGEN05_LD_32X32B_X32(r, ta) \
    asm volatile( \
        "tcgen05.ld.sync.aligned.32x32b.x32.b32 " \
        "{%0, %1, %2, %3, %4, %5, %6, %7, " \
        " %8, %9, %10, %11, %12, %13, %14, %15, " \
        " %16, %17, %18, %19, %20, %21, %22, %23, " \
        " %24, %25, %26, %27, %28, %29, %30, %31}, [%32];" \
        : "=r"((r)[0]),  "=r"((r)[1]),  "=r"((r)[2]),  "=r"((r)[3]), \
          "=r"((r)[4]),  "=r"((r)[5]),  "=r"((r)[6]),  "=r"((r)[7]), \
          "=r"((r)[8]),  "=r"((r)[9]),  "=r"((r)[10]), "=r"((r)[11]), \
          "=r"((r)[12]), "=r"((r)[13]), "=r"((r)[14]), "=r"((r)[15]), \
          "=r"((r)[16]), "=r"((r)[17]), "=r"((r)[18]), "=r"((r)[19]), \
          "=r"((r)[20]), "=r"((r)[21]), "=r"((r)[22]), "=r"((r)[23]), \
          "=r"((r)[24]), "=r"((r)[25]), "=r"((r)[26]), "=r"((r)[27]), \
          "=r"((r)[28]), "=r"((r)[29]), "=r"((r)[30]), "=r"((r)[31]) \
        : "r"(ta))

static constexpr uint64_t SMEM_DESC_BASE_SW128 =
    (uint64_t(2) << 61) | (uint64_t(1) << 46) | (uint64_t(64) << 32) | (uint64_t(1) << 16);
#define MAKE_SMEM_DESC(a) (SMEM_DESC_BASE_SW128 | ((uint64_t)((a) >> 4) & 0x3FFF))
#define SW128(b) ((b) ^ (((b) >> 3) & 0x70))

__device__ __forceinline__ void mma_bf16_ss(uint32_t d_tmem, uint64_t a_desc,
                                            uint64_t b_desc, uint32_t idesc,
                                            uint32_t enable) {
    asm volatile(
        "{\n\t.reg .pred p;\n\t"
        "setp.ne.u32 p, %4, 0;\n\t"
        "tcgen05.mma.cta_group::1.kind::f16 [%0], %1, %2, %3, {%5, %5, %5, %5}, p;\n\t"
        "}"
        :: "r"(d_tmem), "l"(a_desc), "l"(b_desc), "r"(idesc), "r"(enable), "r"(0u)
        : "memory");
}

// idesc: dtype=F32, atype=BF16, btype=BF16, N=128, M=128
static constexpr uint32_t MMA_IDESC =
    (1u << 4) | (1u << 7) | (1u << 10) | ((BN / 8) << 17) | ((BM / 16) << 24);
#endif  // TCG_PATH

// ---------------------------------------------------------------------------
// HMMA helpers (fallback)
// ---------------------------------------------------------------------------
__device__ __forceinline__ void mma16816(float* c, const uint32_t* a, const uint32_t* b) {
    asm volatile(
        "mma.sync.aligned.m16n8k16.row.col.f32.bf16.bf16.f32 "
        "{%0,%1,%2,%3}, {%4,%5,%6,%7}, {%8,%9}, {%0,%1,%2,%3};"
        : "+f"(c[0]), "+f"(c[1]), "+f"(c[2]), "+f"(c[3])
        : "r"(a[0]), "r"(a[1]), "r"(a[2]), "r"(a[3]), "r"(b[0]), "r"(b[1]));
}

__device__ __forceinline__ void ldsm_x4(uint32_t& r0, uint32_t& r1, uint32_t& r2,
                                        uint32_t& r3, uint32_t addr) {
    asm volatile("ldmatrix.sync.aligned.m8n8.x4.shared.b16 {%0,%1,%2,%3}, [%4];"
                 : "=r"(r0), "=r"(r1), "=r"(r2), "=r"(r3) : "r"(addr));
}

// ---------------------------------------------------------------------------
// dist_tc: persistent pipelined tcgen05. grid (16, 32), 512 thr, 1 CTA/SM.
// Schedule: wait load(t) + mbar(t-1) -> issue load(t+1) -> issue MMA(t) ->
// epilogue(t-1). Load overlaps the full MMA+epilogue window.
// SMEM: [0]tmem [8]mb0 [16]mb1 [24]ref, vs[4][128]@32,
//       A@4096 (64KB), B0@69632, B1@135168, red@200704 (8KB) = 208896.
// ---------------------------------------------------------------------------
#define P_VS   32
#define P_A    4096
#define P_B0   69632
#define P_B1   135168
#define P_RED  200704
#define TG_SMEM 208896

#if TCG_PATH
__device__ __forceinline__ void tc_epilogue(char* smem, uint32_t tmem, int sd,
                                            int tp, int nb0, int qb,
                                            int tid, int wid, int lane,
                                            const float* vs4, float4* red,
                                            bool check) {
    const int g = wid >> 2;
    const float* vst = vs4 + (tp & 3) * BN;
    const int gbase = (nb0 + tp) * BN + g * 32;

    uint32_t r[32];
    TCGEN05_LD_32X32B_X32(r, tmem + sd * 128 + g * 32);
    TCGEN05_WAIT_LD();
    TCGEN05_FENCE_BEFORE();

    if (check && wid == 0 && lane == 0) {
        float ref = *reinterpret_cast<float*>(smem + 24);
        float d00 = __uint_as_float(r[0]);
        if (!(fabsf(d00 - ref) <= 0.5f)) atomicOr(&g_tc_bad, 1);
    }

    // 4 independent top-2 accumulators (col j -> acc j&3)
    float v1[4], v2[4];
    int   i1[4], i2[4];
#pragma unroll
    for (int a = 0; a < 4; a++) { v1[a] = 3.4e38f; v2[a] = 3.4e38f; i1[a] = 0; i2[a] = 0; }
#pragma unroll
    for (int j = 0; j < 32; j++) {
        const int a = j & 3;
        float val = vst[g * 32 + j] - 2.0f * __uint_as_float(r[j]);
        top2_upd(val, gbase + j, v1[a], i1[a], v2[a], i2[a]);
    }
#pragma unroll
    for (int a = 1; a < 4; a++)
        pair_merge(v1[0], i1[0], v2[0], i2[0], v1[a], i1[a], v2[a], i2[a]);

    int row = (wid & 3) * 32 + lane;
    red[row * 4 + g] = make_float4(v1[0], v2[0], __int_as_float(i1[0]),
                                   __int_as_float(i2[0]));
    __syncthreads();

    if (tid < BM) {
        float4 e = red[tid * 4 + 0];
        float bv1 = e.x, bv2 = e.y;
        int bi1 = __float_as_int(e.z), bi2 = __float_as_int(e.w);
#pragma unroll
        for (int gg = 1; gg < 4; gg++) {
            float4 f = red[tid * 4 + gg];
            pair_merge(bv1, bi1, bv2, bi2, f.x, __float_as_int(f.z),
                       f.y, __float_as_int(f.w));
        }
        int q = qb * BM + tid;
        int pb = nb0 + tp;
        g_pv1[q * NBLK + pb] = bv1;  g_pi1[q * NBLK + pb] = bi1;
        g_pv2[q * NBLK + pb] = bv2;  g_pi2[q * NBLK + pb] = bi2;
    }
}
#endif

__global__ void __launch_bounds__(NT, 1) dist_tc_kernel() {
#if TCG_PATH
    extern __shared__ char smem[];
    uint32_t sb = smem_u32(smem);
    const int tid = threadIdx.x;
    const int wid = tid >> 5;
    const int lane = tid & 31;
    const int qb = blockIdx.x;
    const int nb0 = blockIdx.y * TPC;

    if (wid == 0) {
        TCGEN05_ALLOC(sb + 0, 256);
        TCGEN05_RELINQUISH();
    }
    if (tid == 0) { MBARRIER_INIT(sb + 8, 1); MBARRIER_INIT(sb + 16, 1); }
    __syncthreads();
    uint32_t tmem;
    asm volatile("ld.shared.b32 %0, [%1];" : "=r"(tmem) : "r"(sb + 0));

    float* vs4 = reinterpret_cast<float*>(smem + P_VS);     // [4][128]
    float4* red = reinterpret_cast<float4*>(smem + P_RED);  // [128][4]

    // Per-thread tile-unit mapping: 4096 16B units, 8 per thread
    uint32_t swoff[8];
#pragma unroll
    for (int i = 0; i < 8; i++) {
        int u = tid + NT * i;
        int row = u >> 5, cu = u & 31;
        int ac = cu >> 3, iu = cu & 7;
        int ar = row >> 3, ir = row & 7;
        uint32_t byt = ((uint32_t)(ac * 16 + ar) << 10) + (ir << 7) + (iu << 4);
        swoff[i] = SW128(byt);
    }

    // Stationary A tile
    {
        const uint4* src = reinterpret_cast<const uint4*>(g_Qb + (size_t)qb * BM * DIM);
#pragma unroll
        for (int i = 0; i < 8; i++)
            *reinterpret_cast<uint4*>(smem + P_A + swoff[i]) = src[tid + NT * i];
    }
    // Prologue: load(0) -> B0, vsq(0)
    {
        const char* src = reinterpret_cast<const char*>(g_Vb + (size_t)nb0 * BN * DIM);
#pragma unroll
        for (int i = 0; i < 8; i++)
            CP_ASYNC16(sb + P_B0 + swoff[i], src + (tid + NT * i) * 16);
        if (tid < BN) vs4[tid] = g_vsq[nb0 * BN + tid];
        CP_COMMIT();
    }

    const uint64_t ad = MAKE_SMEM_DESC(sb + P_A);
    const uint64_t bdesc[2] = { MAKE_SMEM_DESC(sb + P_B0), MAKE_SMEM_DESC(sb + P_B1) };
    int ph0 = 0, ph1 = 0;

#pragma unroll 1
    for (int t = 0; t < TPC; t++) {
        const int s = t & 1;

        CP_WAIT(0);
        FENCE_PROXY_ASYNC();
        __syncthreads();

        // wait MMA(t-1): frees B[1-s] for reload, makes D[1-s] readable
        if (t > 0) {
            if (s) { MBARRIER_WAIT_PARITY(sb + 8,  ph0); ph0 ^= 1; }
            else   { MBARRIER_WAIT_PARITY(sb + 16, ph1); ph1 ^= 1; }
            TCGEN05_FENCE_AFTER();
        }

        // tile-0 reference dot for self-validation (B0 valid, before MMA)
        if (t == 0 && wid == 0) {
            float ref = 0.f;
#pragma unroll
            for (int t8 = 0; t8 < 8; t8++) {
                int k = lane * 8 + t8;
                uint32_t off = ((uint32_t)(k >> 6) << 14) + (uint32_t)(k & 63) * 2;
                float a = __bfloat162float(*reinterpret_cast<const __nv_bfloat16*>(smem + P_A + off));
                float b = __bfloat162float(*reinterpret_cast<const __nv_bfloat16*>(smem + P_B0 + off));
                ref += a * b;
            }
#pragma unroll
            for (int o = 16; o; o >>= 1) ref += __shfl_xor_sync(0xFFFFFFFFu, ref, o);
            if (lane == 0) *reinterpret_cast<float*>(smem + 24) = ref;
        }

        // issue load(t+1) into B[1-s] NOW (full MMA+epilogue overlap window)
        if (t + 1 < TPC) {
            const char* src = reinterpret_cast<const char*>(
                g_Vb + (size_t)(nb0 + t + 1) * BN * DIM);
            uint32_t base = sb + ((1 - s) ? P_B1 : P_B0);
#pragma unroll
            for (int i = 0; i < 8; i++)
                CP_ASYNC16(base + swoff[i], src + (tid + NT * i) * 16);
            if (tid < BN) vs4[((t + 1) & 3) * BN + tid] = g_vsq[(nb0 + t + 1) * BN + tid];
            CP_COMMIT();
        }

        // issue MMA(t): B[s] -> D[s]
        if (wid == 0) {
            TCGEN05_FENCE_AFTER();
            if (elect_one_pred()) {
#pragma unroll
                for (int k = 0; k < 16; k++) {
                    uint64_t off = (uint64_t)((k >> 2) * 1024 + (k & 3) * 2);
                    mma_bf16_ss(tmem + s * 128, ad + off, bdesc[s] + off, MMA_IDESC,
                                (uint32_t)(k > 0));
                }
                TCGEN05_COMMIT(sb + (s ? 16 : 8));
            }
        }

        // epilogue(t-1) from D[1-s]
        if (t > 0)
            tc_epilogue(smem, tmem, 1 - s, t - 1, nb0, qb, tid, wid, lane,
                        vs4, red, (t - 1) == 0);
    }

    // tail: wait MMA(TPC-1), epilogue(TPC-1)
    {
        const int sd = (TPC - 1) & 1;
        if (sd) { MBARRIER_WAIT_PARITY(sb + 16, ph1); ph1 ^= 1; }
        else    { MBARRIER_WAIT_PARITY(sb + 8,  ph0); ph0 ^= 1; }
        TCGEN05_FENCE_AFTER();
        tc_epilogue(smem, tmem, sd, TPC - 1, nb0, qb, tid, wid, lane,
                    vs4, red, false);
    }
    __syncthreads();
    if (wid == 0) TCGEN05_DEALLOC(tmem, 256);
#else
    if (threadIdx.x == 0 && blockIdx.x == 0 && blockIdx.y == 0) g_tc_bad = 1;
#endif
}

// ---------------------------------------------------------------------------
// dist_fb: proven HMMA kernel; runs only if tcgen05 invalid.
// ---------------------------------------------------------------------------
__global__ void __launch_bounds__(256, 2) dist_fb_kernel() {
    if (*(volatile int*)&g_tc_bad == 0) return;

    __shared__ __nv_bfloat16 As[2][BM][40];
    __shared__ __nv_bfloat16 Bs[2][BN][40];
    __shared__ float vs[BN];
    __shared__ float4 red[BM][2];

    const int tid = threadIdx.x;
    const int wid = tid >> 5;
    const int lane = tid & 31;
    const int g = lane >> 2, tg = lane & 3;
    const int wm = wid >> 1, wn = wid & 1;
    const int qb = blockIdx.x;
    const int nb = blockIdx.y;

    const size_t qbase = (size_t)qb * BM * DIM;
    const size_t nbase = (size_t)nb * BN * DIM;

    if (tid < BN) vs[tid] = g_vsq[nb * BN + tid];

    const int r0a = tid >> 2, q0 = (tid & 3) * 8;
    const int r1a = (tid + 256) >> 2, q1 = ((tid + 256) & 3) * 8;

    uint32_t asA[2], asB[2], asA1[2], asB1[2];
#pragma unroll
    for (int s = 0; s < 2; s++) {
        asA[s]  = smem_u32(&As[s][r0a][q0]);
        asA1[s] = smem_u32(&As[s][r1a][q1]);
        asB[s]  = smem_u32(&Bs[s][r0a][q0]);
        asB1[s] = smem_u32(&Bs[s][r1a][q1]);
    }

#pragma unroll
    for (int c = 0; c < 2; c++) {
        const int c0 = c * BK;
        CP_ASYNC16(asA[c],  g_Qb + qbase + r0a * DIM + c0 + q0);
        CP_ASYNC16(asA1[c], g_Qb + qbase + r1a * DIM + c0 + q1);
        CP_ASYNC16(asB[c],  g_Vb + nbase + r0a * DIM + c0 + q0);
        CP_ASYNC16(asB1[c], g_Vb + nbase + r1a * DIM + c0 + q1);
        CP_COMMIT();
    }

    const int a_row = wm * 32 + ((lane >> 3) & 1) * 8 + (lane & 7);
    const int a_col = (lane >> 4) * 8;
    const int b_ni_off = (lane >> 4) & 1;
    const int b_kh = ((lane >> 3) & 1) * 8;
    const int b_r = lane & 7;

    float acc[2][8][4];
#pragma unroll
    for (int mi = 0; mi < 2; mi++)
#pragma unroll
        for (int ni = 0; ni < 8; ni++)
#pragma unroll
            for (int e = 0; e < 4; e++) acc[mi][ni][e] = 0.f;

#pragma unroll 1
    for (int c = 0; c < 8; c++) {
        if (c + 2 < 8) { CP_WAIT(1); } else { CP_WAIT(0); }
        __syncthreads();

        const int s = c & 1;
        const uint32_t aBase = smem_u32(&As[s][0][0]);
        const uint32_t bBase = smem_u32(&Bs[s][0][0]);

#pragma unroll
        for (int ks = 0; ks < BK; ks += 16) {
            uint32_t a[2][4];
#pragma unroll
            for (int mi = 0; mi < 2; mi++) {
                uint32_t addr = aBase + (uint32_t)((a_row + mi * 16) * 80 + (ks + a_col) * 2);
                ldsm_x4(a[mi][0], a[mi][1], a[mi][2], a[mi][3], addr);
            }
            uint32_t b[8][2];
#pragma unroll
            for (int p = 0; p < 8; p += 2) {
                int ni = p + b_ni_off;
                uint32_t addr = bBase + (uint32_t)((wn * 64 + ni * 8 + b_r) * 80 + (ks + b_kh) * 2);
                ldsm_x4(b[p][0], b[p][1], b[p + 1][0], b[p + 1][1], addr);
            }
#pragma unroll
            for (int mi = 0; mi < 2; mi++)
#pragma unroll
                for (int ni = 0; ni < 8; ni++)
                    mma16816(acc[mi][ni], a[mi], b[ni]);
        }
        __syncthreads();

        if (c + 2 < 8) {
            const int c0 = (c + 2) * BK;
            CP_ASYNC16(asA[s],  g_Qb + qbase + r0a * DIM + c0 + q0);
            CP_ASYNC16(asA1[s], g_Qb + qbase + r1a * DIM + c0 + q1);
            CP_ASYNC16(asB[s],  g_Vb + nbase + r0a * DIM + c0 + q0);
            CP_ASYNC16(asB1[s], g_Vb + nbase + r1a * DIM + c0 + q1);
            CP_COMMIT();
        }
    }

    const int gcol0 = nb * BN;
#pragma unroll
    for (int mi = 0; mi < 2; mi++) {
#pragma unroll
        for (int h = 0; h < 2; h++) {
            float v1 = 3.4e38f, v2 = 3.4e38f;
            int i1 = 0, i2 = 0;
#pragma unroll
            for (int ni = 0; ni < 8; ni++) {
                int c0 = wn * 64 + ni * 8 + tg * 2;
                float x0 = vs[c0]     - 2.0f * acc[mi][ni][h * 2];
                float x1 = vs[c0 + 1] - 2.0f * acc[mi][ni][h * 2 + 1];
                top2_upd(x0, gcol0 + c0,     v1, i1, v2, i2);
                top2_upd(x1, gcol0 + c0 + 1, v1, i1, v2, i2);
            }
            top2_shfl_merge(v1, i1, v2, i2, 1);
            top2_shfl_merge(v1, i1, v2, i2, 2);
            if (tg == 0) {
                int row = wm * 32 + mi * 16 + h * 8 + g;
                red[row][wn] = make_float4(v1, v2, __int_as_float(i1), __int_as_float(i2));
            }
        }
    }
    __syncthreads();

    if (tid < BM) {
        float4 e0 = red[tid][0];
        float4 e1 = red[tid][1];
        float v1 = e0.x, v2 = e0.y;
        int i1 = __float_as_int(e0.z), i2 = __float_as_int(e0.w);
        pair_merge(v1, i1, v2, i2, e1.x, __float_as_int(e1.z),
                   e1.y, __float_as_int(e1.w));
        int q = qb * BM + tid;
        g_pv1[q * NBLK + nb] = v1;  g_pi1[q * NBLK + nb] = i1;
        g_pv2[q * NBLK + nb] = v2;  g_pi2[q * NBLK + nb] = i2;
    }
}

// ---------------------------------------------------------------------------
// refine: warp-per-query (unchanged)
// ---------------------------------------------------------------------------
__global__ void __launch_bounds__(256) refine_kernel(const float* __restrict__ query,
                                                     const float* __restrict__ vectors,
                                                     float* __restrict__ out) {
    const int lane = threadIdx.x & 31;
    const int m = blockIdx.x * 8 + (threadIdx.x >> 5);

    const float* qr = query + (size_t)m * DIM;
    float4 qa = *reinterpret_cast<const float4*>(qr + lane * 8);
    float4 qb = *reinterpret_cast<const float4*>(qr + lane * 8 + 4);

    const float4* p1 = reinterpret_cast<const float4*>(g_pv1 + (size_t)m * NBLK);
    float lm = 3.4e38f;
#pragma unroll
    for (int j = 0; j < 8; j++) {
        float4 v = p1[lane + 32 * j];
        lm = fminf(lm, fminf(fminf(v.x, v.y), fminf(v.z, v.w)));
    }
#pragma unroll
    for (int o = 16; o; o >>= 1) lm = fminf(lm, __shfl_xor_sync(0xFFFFFFFFu, lm, o));
    const float thresh = lm + MARGIN;

    float bestv = 3.4e38f;
    int   besti = 0x7fffffff;
    const float* r1 = g_pv1 + (size_t)m * NBLK;
    const float* r2 = g_pv2 + (size_t)m * NBLK;
#pragma unroll 1
    for (int e = lane; e < 2 * NBLK; e += 32) {
        float pv = (e < NBLK) ? r1[e] : r2[e - NBLK];
        unsigned bal = __ballot_sync(0xFFFFFFFFu, pv <= thresh);
        while (bal) {
            int src = __ffs(bal) - 1;
            bal &= bal - 1;
            int pe = __shfl_sync(0xFFFFFFFFu, e, src);
            int pi = (pe < NBLK) ? g_pi1[(size_t)m * NBLK + pe]
                                 : g_pi2[(size_t)m * NBLK + pe - NBLK];
            const float* vr = vectors + (size_t)pi * DIM;
            float4 va = *reinterpret_cast<const float4*>(vr + lane * 8);
            float4 vb = *reinterpret_cast<const float4*>(vr + lane * 8 + 4);
            float d0 = qa.x - va.x, d1 = qa.y - va.y, d2 = qa.z - va.z, d3 = qa.w - va.w;
            float e0 = qb.x - vb.x, e1 = qb.y - vb.y, e2 = qb.z - vb.z, e3 = qb.w - vb.w;
            float s = d0 * d0;
            s = fmaf(d1, d1, s); s = fmaf(d2, d2, s); s = fmaf(d3, d3, s);
            s = fmaf(e0, e0, s); s = fmaf(e1, e1, s); s = fmaf(e2, e2, s);
            s = fmaf(e3, e3, s);
#pragma unroll
            for (int o = 16; o; o >>= 1) s += __shfl_xor_sync(0xFFFFFFFFu, s, o);
            if (s < bestv || (s == bestv && pi < besti)) { bestv = s; besti = pi; }
        }
    }
    if (lane == 0) out[m] = (float)besti;
}

// ---------------------------------------------------------------------------
extern "C" void kernel_launch(void* const* d_in, const int* in_sizes, int n_in,
                              void* d_out, int out_size) {
    const float* query = nullptr;
    const float* vectors = nullptr;
    for (int i = 0; i < n_in; i++) {
        long long sz = in_sizes[i];
        if (sz == (long long)M_Q * DIM || sz == (long long)M_Q * DIM * 4) {
            if (!query) query = (const float*)d_in[i];
        } else if (sz == (long long)N_V * DIM || sz == (long long)N_V * DIM * 4) {
            if (!vectors) vectors = (const float*)d_in[i];
        }
    }
    if (!query)   query   = (const float*)d_in[0];
    if (!vectors) vectors = (const float*)d_in[1];

    float* out = (float*)d_out;

    cudaFuncSetAttribute(dist_tc_kernel, cudaFuncAttributeMaxDynamicSharedMemorySize, TG_SMEM);

    zero_flag_kernel<<<1, 1>>>();
    convert_vec_kernel<<<(N_V * 32) / 256, 256>>>(vectors);
    convert_q_kernel<<<(M_Q * 32) / 256, 256>>>(query);
    dist_tc_kernel<<<dim3(QBLK, GY), NT, TG_SMEM>>>();
    dist_fb_kernel<<<dim3(QBLK, NBLK), 256>>>();
    refine_kernel<<<M_Q / 8, 256>>>(query, vectors, out);
}